// round 3
// baseline (speedup 1.0000x reference)
#include <cuda_runtime.h>
#include <cuda_bf16.h>
#include <math.h>

// Problem constants (fixed by the dataset)
#define NMAX 100000
#define EMAX 1600000
#define TMAX (NMAX + EMAX)
#define INF 128
#define HID 64
#define SCAN_T 1024

// ---------------- scratch (device globals; no allocation allowed) ------------
__device__ __align__(128) float g_h[(size_t)NMAX * HID];      // 25.6 MB
__device__ __align__(128) float g_asrc[NMAX];
__device__ __align__(128) float g_adst[NMAX];
__device__ __align__(128) float g_denom[NMAX];
__device__ __align__(128) float g_ew[TMAX];
__device__ __align__(128) float g_colsum[HID];
__device__ __align__(128) int   g_deg[NMAX];
__device__ __align__(128) int   g_off[NMAX + 1];
__device__ __align__(128) int   g_cur[NMAX];
__device__ __align__(128) int   g_bsrc[TMAX];
__device__ __align__(128) float g_bw[TMAX];

// ---------------- zero small scratch -----------------------------------------
__global__ void zero_kernel(int N) {
    int i = blockIdx.x * blockDim.x + threadIdx.x;
    for (; i < N; i += gridDim.x * blockDim.x) {
        g_denom[i] = 0.f;
        g_deg[i] = 0;
    }
    if (blockIdx.x == 0 && threadIdx.x < HID) g_colsum[threadIdx.x] = 0.f;
}

// ---------------- GEMM: h = x @ W  (N x 128) @ (128 x 64) -------------------
__global__ __launch_bounds__(256) void gemm_kernel(
    const float* __restrict__ x, const float* __restrict__ W, int N)
{
    __shared__ float xs[32][129];
    __shared__ float ws[32][64];

    const int tid = threadIdx.x;
    const int cx  = tid & 15;
    const int ry  = tid >> 4;
    const int rowBase = blockIdx.x * 128;

    float acc[8][4];
#pragma unroll
    for (int i = 0; i < 8; i++)
#pragma unroll
        for (int c = 0; c < 4; c++) acc[i][c] = 0.f;

    for (int kc = 0; kc < INF; kc += 32) {
#pragma unroll
        for (int idx = tid; idx < 128 * 32; idx += 256) {
            int r = idx >> 5, k = idx & 31;
            int gr = rowBase + r;
            xs[k][r] = (gr < N) ? x[(size_t)gr * INF + kc + k] : 0.f;
        }
#pragma unroll
        for (int idx = tid; idx < 32 * 64; idx += 256) {
            int k = idx >> 6, j = idx & 63;
            ws[k][j] = W[(size_t)(kc + k) * HID + j];
        }
        __syncthreads();

#pragma unroll
        for (int k = 0; k < 32; k++) {
            float4 wv = *(const float4*)&ws[k][cx * 4];
#pragma unroll
            for (int i = 0; i < 8; i++) {
                float xv = xs[k][ry + 16 * i];
                acc[i][0] += xv * wv.x;
                acc[i][1] += xv * wv.y;
                acc[i][2] += xv * wv.z;
                acc[i][3] += xv * wv.w;
            }
        }
        __syncthreads();
    }

#pragma unroll
    for (int i = 0; i < 8; i++) {
        int r = rowBase + ry + 16 * i;
        if (r < N) {
            float4 v = make_float4(acc[i][0], acc[i][1], acc[i][2], acc[i][3]);
            *(float4*)&g_h[(size_t)r * HID + cx * 4] = v;
        }
    }
}

// ---------------- per-node attention scores ----------------------------------
__global__ __launch_bounds__(256) void scores_kernel(
    const float* __restrict__ att_src, const float* __restrict__ att_dst, int N)
{
    int gw   = (blockIdx.x * blockDim.x + threadIdx.x) >> 5;
    int lane = threadIdx.x & 31;
    if (gw >= N) return;
    const float* hrow = g_h + (size_t)gw * HID;
    float h0 = hrow[lane], h1 = hrow[lane + 32];
    float s = h0 * att_src[lane] + h1 * att_src[lane + 32];
    float d = h0 * att_dst[lane] + h1 * att_dst[lane + 32];
#pragma unroll
    for (int o = 16; o; o >>= 1) {
        s += __shfl_xor_sync(0xFFFFFFFFu, s, o);
        d += __shfl_xor_sync(0xFFFFFFFFu, d, o);
    }
    if (lane == 0) { g_asrc[gw] = s; g_adst[gw] = d; }
}

// ---------------- edge pass 1: w=exp(lrelu(logit)), denom, degree ------------
// softmax max-shift omitted: logits are O(10) here, exp is fp32-safe and alpha
// is shift-invariant, so result matches the reference within tolerance.
__global__ __launch_bounds__(256) void edge1_kernel(
    const int* __restrict__ ei, int E, int N)
{
    int T = E + N;
    for (int e = blockIdx.x * blockDim.x + threadIdx.x; e < T;
         e += gridDim.x * blockDim.x) {
        int s, d;
        if (e < E) { s = ei[e]; d = ei[E + e]; }
        else       { s = d = e - E; }
        float l = g_asrc[s] + g_adst[d];
        l = (l > 0.f) ? l : 0.2f * l;
        float w = expf(l);
        g_ew[e] = w;
        atomicAdd(&g_denom[d], w);
        atomicAdd(&g_deg[d], 1);
    }
}

// ---------------- exclusive scan of degrees -> offsets + cursors -------------
// single block, 1024 threads; each thread scans a contiguous chunk
__global__ __launch_bounds__(SCAN_T) void scan_kernel(int N)
{
    __shared__ int sums[SCAN_T];
    int tid = threadIdx.x;
    int chunk = (N + SCAN_T - 1) / SCAN_T;
    int begin = tid * chunk;
    int end   = min(begin + chunk, N);

    int s = 0;
    for (int i = begin; i < end; i++) s += g_deg[i];
    sums[tid] = s;
    __syncthreads();

    // Hillis-Steele inclusive scan over sums
    for (int off = 1; off < SCAN_T; off <<= 1) {
        int t = (tid >= off) ? sums[tid - off] : 0;
        __syncthreads();
        sums[tid] += t;
        __syncthreads();
    }

    int run = sums[tid] - s;   // exclusive base for this chunk
    for (int i = begin; i < end; i++) {
        int dg = g_deg[i];
        g_off[i] = run;
        g_cur[i] = run;
        run += dg;
    }
    if (tid == SCAN_T - 1) g_off[N] = sums[SCAN_T - 1];
}

// ---------------- scatter edges into dst buckets -----------------------------
__global__ __launch_bounds__(256) void scatter_kernel(
    const int* __restrict__ ei, int E, int N)
{
    int T = E + N;
    for (int e = blockIdx.x * blockDim.x + threadIdx.x; e < T;
         e += gridDim.x * blockDim.x) {
        int s, d;
        if (e < E) { s = ei[e]; d = ei[E + e]; }
        else       { s = d = e - E; }
        float w = g_ew[e];
        int pos = atomicAdd(&g_cur[d], 1);
        g_bsrc[pos] = s;
        g_bw[pos]   = w;
    }
}

// ---------------- gather: per-node weighted sum + fused epilogue --------------
// warp per node; lane handles features (2*lane, 2*lane+1) via float2.
// agg = (sum_e w_e * h[src_e]) / denom ; then bias+relu and column-sum.
__global__ __launch_bounds__(256) void gather_kernel(
    const float* __restrict__ bias, int N)
{
    __shared__ float csum[HID];
    if (threadIdx.x < HID) csum[threadIdx.x] = 0.f;
    __syncthreads();

    int gw   = (blockIdx.x * blockDim.x + threadIdx.x) >> 5;
    int lane = threadIdx.x & 31;

    if (gw < N) {
        int beg = g_off[gw];
        int end = g_off[gw + 1];
        const float2* __restrict__ h2 = (const float2*)g_h;

        float2 acc = make_float2(0.f, 0.f);
        for (int k = beg; k < end; k++) {
            int   s = g_bsrc[k];
            float w = g_bw[k];
            float2 hv = __ldg(&h2[(size_t)s * 32 + lane]);
            acc.x += w * hv.x;
            acc.y += w * hv.y;
        }
        float inv = 1.f / g_denom[gw];
        float v0 = fmaxf(acc.x * inv + bias[2 * lane],     0.f);
        float v1 = fmaxf(acc.y * inv + bias[2 * lane + 1], 0.f);
        atomicAdd(&csum[2 * lane],     v0);
        atomicAdd(&csum[2 * lane + 1], v1);
    }
    __syncthreads();
    if (threadIdx.x < HID) atomicAdd(&g_colsum[threadIdx.x], csum[threadIdx.x]);
}

// ---------------- final: out = (colsum/N) @ W_lin + b_lin --------------------
__global__ void final_kernel(const float* __restrict__ W_lin,
                             const float* __restrict__ b_lin,
                             float* __restrict__ out, float invN)
{
    int j = threadIdx.x;   // 64 threads
    float acc = b_lin[j];
#pragma unroll
    for (int k = 0; k < 64; k++)
        acc += (g_colsum[k] * invN) * W_lin[k * 64 + j];
    out[j] = acc;
}

// ---------------- launch -----------------------------------------------------
extern "C" void kernel_launch(void* const* d_in, const int* in_sizes, int n_in,
                              void* d_out, int out_size)
{
    const float* x       = (const float*)d_in[0];
    const int*   ei      = (const int*)d_in[1];
    const float* W       = (const float*)d_in[2];
    const float* att_src = (const float*)d_in[3];
    const float* att_dst = (const float*)d_in[4];
    const float* bias    = (const float*)d_in[5];
    const float* W_lin   = (const float*)d_in[6];
    const float* b_lin   = (const float*)d_in[7];
    float*       out     = (float*)d_out;

    const int N = in_sizes[0] / INF;       // 100000
    const int E = in_sizes[1] / 2;         // 1600000
    const int T = E + N;

    zero_kernel<<<256, 256>>>(N);

    gemm_kernel<<<(N + 127) / 128, 256>>>(x, W, N);

    scores_kernel<<<(N + 7) / 8, 256>>>(att_src, att_dst, N);

    edge1_kernel<<<(T + 255) / 256, 256>>>(ei, E, N);

    scan_kernel<<<1, SCAN_T>>>(N);

    scatter_kernel<<<(T + 255) / 256, 256>>>(ei, E, N);

    long long threadsG = (long long)N * 32;
    int blocksG = (int)((threadsG + 255) / 256);
    gather_kernel<<<blocksG, 256>>>(bias, N);

    final_kernel<<<1, 64>>>(W_lin, b_lin, out, 1.0f / (float)N);
}

// round 4
// speedup vs baseline: 1.7376x; 1.7376x over previous
#include <cuda_runtime.h>
#include <cuda_bf16.h>
#include <math.h>

// Problem constants (fixed by the dataset)
#define NMAX 100000
#define EMAX 1600000
#define TMAX (NMAX + EMAX)
#define INF 128
#define HID 64

// ---------------- scratch (device globals; no allocation allowed) ------------
__device__ __align__(128) float g_h[(size_t)NMAX * HID];      // 25.6 MB
__device__ __align__(128) float g_agg[(size_t)NMAX * HID];    // 25.6 MB (unnormalized)
__device__ __align__(128) float g_asrc[NMAX];
__device__ __align__(128) float g_adst[NMAX];
__device__ __align__(128) float g_denom[NMAX];
__device__ __align__(128) float g_colsum[HID];

// ---------------- vector reduction helper ------------------------------------
__device__ __forceinline__ void red_add_v4(float* p, float a, float b, float c, float d) {
    asm volatile("red.global.add.v4.f32 [%0], {%1, %2, %3, %4};"
                 :: "l"(p), "f"(a), "f"(b), "f"(c), "f"(d) : "memory");
}

// ---------------- zero scratch ------------------------------------------------
__global__ void zero_kernel(int N) {
    size_t total = (size_t)N * HID;
    for (size_t i = (size_t)blockIdx.x * blockDim.x + threadIdx.x; i < total;
         i += (size_t)gridDim.x * blockDim.x)
        g_agg[i] = 0.f;
    for (int i = blockIdx.x * blockDim.x + threadIdx.x; i < N;
         i += gridDim.x * blockDim.x)
        g_denom[i] = 0.f;
    if (blockIdx.x == 0 && threadIdx.x < HID) g_colsum[threadIdx.x] = 0.f;
}

// ---------------- GEMM: h = x @ W, fused attention scores --------------------
// Block tile 128x64, 256 threads, 8x4 per thread.
// Epilogue: a_src[r] = h[r]·att_src, a_dst[r] = h[r]·att_dst via 16-lane shfl.
__global__ __launch_bounds__(256) void gemm_kernel(
    const float* __restrict__ x, const float* __restrict__ W,
    const float* __restrict__ att_src, const float* __restrict__ att_dst, int N)
{
    __shared__ float xs[32][129];
    __shared__ float ws[32][64];

    const int tid = threadIdx.x;
    const int cx  = tid & 15;
    const int ry  = tid >> 4;
    const int rowBase = blockIdx.x * 128;

    float acc[8][4];
#pragma unroll
    for (int i = 0; i < 8; i++)
#pragma unroll
        for (int c = 0; c < 4; c++) acc[i][c] = 0.f;

    // attention weights for my 4 columns
    float as4[4], ad4[4];
#pragma unroll
    for (int c = 0; c < 4; c++) {
        as4[c] = att_src[cx * 4 + c];
        ad4[c] = att_dst[cx * 4 + c];
    }

    for (int kc = 0; kc < INF; kc += 32) {
#pragma unroll
        for (int idx = tid; idx < 128 * 32; idx += 256) {
            int r = idx >> 5, k = idx & 31;
            int gr = rowBase + r;
            xs[k][r] = (gr < N) ? x[(size_t)gr * INF + kc + k] : 0.f;
        }
#pragma unroll
        for (int idx = tid; idx < 32 * 64; idx += 256) {
            int k = idx >> 6, j = idx & 63;
            ws[k][j] = W[(size_t)(kc + k) * HID + j];
        }
        __syncthreads();

#pragma unroll
        for (int k = 0; k < 32; k++) {
            float4 wv = *(const float4*)&ws[k][cx * 4];
#pragma unroll
            for (int i = 0; i < 8; i++) {
                float xv = xs[k][ry + 16 * i];
                acc[i][0] += xv * wv.x;
                acc[i][1] += xv * wv.y;
                acc[i][2] += xv * wv.z;
                acc[i][3] += xv * wv.w;
            }
        }
        __syncthreads();
    }

#pragma unroll
    for (int i = 0; i < 8; i++) {
        int r = rowBase + ry + 16 * i;
        if (r < N) {
            float4 v = make_float4(acc[i][0], acc[i][1], acc[i][2], acc[i][3]);
            *(float4*)&g_h[(size_t)r * HID + cx * 4] = v;

            float ps = acc[i][0] * as4[0] + acc[i][1] * as4[1] +
                       acc[i][2] * as4[2] + acc[i][3] * as4[3];
            float pd = acc[i][0] * ad4[0] + acc[i][1] * ad4[1] +
                       acc[i][2] * ad4[2] + acc[i][3] * ad4[3];
#pragma unroll
            for (int o = 8; o; o >>= 1) {   // reduce over the 16-lane col group
                ps += __shfl_xor_sync(0xFFFFFFFFu, ps, o);
                pd += __shfl_xor_sync(0xFFFFFFFFu, pd, o);
            }
            if (cx == 0) { g_asrc[r] = ps; g_adst[r] = pd; }
        }
    }
}

// ---------------- single edge pass -------------------------------------------
// Half-warp per edge (lanes 0-15 edge 2w, lanes 16-31 edge 2w+1).
// w = exp(leaky_relu(a_src[s] + a_dst[d]))  (max-shift omitted: logits O(10),
// alpha is shift-invariant, fp32-safe).
// agg[d] += w * h[s] via red.global.add.v4.f32; denom[d] += w (sub-lane 0).
__global__ __launch_bounds__(256) void edge_kernel(
    const int* __restrict__ ei, int E, int N)
{
    const int T = E + N;
    const int lane = threadIdx.x & 31;
    const int sub  = lane & 15;
    const int half = lane >> 4;

    long long warpId = ((long long)blockIdx.x * blockDim.x + threadIdx.x) >> 5;
    long long e = warpId * 2 + half;
    if (e >= T) return;

    int s, d;
    if (e < E) { s = ei[e]; d = ei[E + e]; }
    else       { s = d = (int)(e - E); }

    float l = g_asrc[s] + g_adst[d];
    l = (l > 0.f) ? l : 0.2f * l;
    float w = expf(l);

    float4 hv = __ldg(&((const float4*)g_h)[(size_t)s * 16 + sub]);
    float* ap = g_agg + (size_t)d * HID + sub * 4;
    red_add_v4(ap, w * hv.x, w * hv.y, w * hv.z, w * hv.w);

    if (sub == 0) atomicAdd(&g_denom[d], w);
}

// ---------------- colsum of relu(agg/denom + bias) ---------------------------
__global__ __launch_bounds__(256) void colsum_kernel(
    const float* __restrict__ bias, int N)
{
    int j = threadIdx.x & 63;
    int rstart = blockIdx.x * 4 + (threadIdx.x >> 6);
    float b = bias[j];
    float acc = 0.f;
    for (int r = rstart; r < N; r += gridDim.x * 4) {
        float inv = 1.f / g_denom[r];
        float v = g_agg[(size_t)r * HID + j] * inv + b;
        acc += (v > 0.f) ? v : 0.f;
    }
    __shared__ float sm[256];
    sm[threadIdx.x] = acc;
    __syncthreads();
    if (threadIdx.x < 64)
        atomicAdd(&g_colsum[j], sm[threadIdx.x] + sm[threadIdx.x + 64] +
                                sm[threadIdx.x + 128] + sm[threadIdx.x + 192]);
}

// ---------------- final: out = (colsum/N) @ W_lin + b_lin --------------------
__global__ void final_kernel(const float* __restrict__ W_lin,
                             const float* __restrict__ b_lin,
                             float* __restrict__ out, float invN)
{
    int j = threadIdx.x;   // 64 threads
    float acc = b_lin[j];
#pragma unroll
    for (int k = 0; k < 64; k++)
        acc += (g_colsum[k] * invN) * W_lin[k * 64 + j];
    out[j] = acc;
}

// ---------------- launch -----------------------------------------------------
extern "C" void kernel_launch(void* const* d_in, const int* in_sizes, int n_in,
                              void* d_out, int out_size)
{
    const float* x       = (const float*)d_in[0];
    const int*   ei      = (const int*)d_in[1];
    const float* W       = (const float*)d_in[2];
    const float* att_src = (const float*)d_in[3];
    const float* att_dst = (const float*)d_in[4];
    const float* bias    = (const float*)d_in[5];
    const float* W_lin   = (const float*)d_in[6];
    const float* b_lin   = (const float*)d_in[7];
    float*       out     = (float*)d_out;

    const int N = in_sizes[0] / INF;       // 100000
    const int E = in_sizes[1] / 2;         // 1600000
    const int T = E + N;

    zero_kernel<<<1024, 256>>>(N);

    gemm_kernel<<<(N + 127) / 128, 256>>>(x, W, att_src, att_dst, N);

    long long warps = ((long long)T + 1) / 2;          // 2 edges per warp
    long long threads = warps * 32;
    int blocks = (int)((threads + 255) / 256);
    edge_kernel<<<blocks, 256>>>(ei, E, N);

    colsum_kernel<<<1024, 256>>>(bias, N);

    final_kernel<<<1, 64>>>(W_lin, b_lin, out, 1.0f / (float)N);
}

// round 5
// speedup vs baseline: 1.7900x; 1.0302x over previous
#include <cuda_runtime.h>
#include <cuda_bf16.h>
#include <math.h>

// Problem constants (fixed by the dataset)
#define NMAX 100000
#define EMAX 1600000
#define TMAX (NMAX + EMAX)
#define INF 128
#define HID 64

// ---------------- scratch (device globals; no allocation allowed) ------------
// Invariant: g_agg, g_denom, g_colsum are ZERO on entry to kernel_launch
// (zero at module load; each pass that consumes them re-zeroes for next replay).
__device__ __align__(128) float g_h[(size_t)NMAX * HID];      // 25.6 MB
__device__ __align__(128) float g_agg[(size_t)NMAX * HID];    // 25.6 MB (unnormalized)
__device__ __align__(128) float g_asrc[NMAX];
__device__ __align__(128) float g_adst[NMAX];
__device__ __align__(128) float g_denom[NMAX];
__device__ __align__(128) float g_colsum[HID];

// ---------------- vector reduction helper ------------------------------------
__device__ __forceinline__ void red_add_v4(float* p, float a, float b, float c, float d) {
    asm volatile("red.global.add.v4.f32 [%0], {%1, %2, %3, %4};"
                 :: "l"(p), "f"(a), "f"(b), "f"(c), "f"(d) : "memory");
}

// ---------------- GEMM: h = x @ W, fused attention scores --------------------
__global__ __launch_bounds__(256) void gemm_kernel(
    const float* __restrict__ x, const float* __restrict__ W,
    const float* __restrict__ att_src, const float* __restrict__ att_dst, int N)
{
    __shared__ float xs[32][129];
    __shared__ float ws[32][64];

    const int tid = threadIdx.x;
    const int cx  = tid & 15;
    const int ry  = tid >> 4;
    const int rowBase = blockIdx.x * 128;

    float acc[8][4];
#pragma unroll
    for (int i = 0; i < 8; i++)
#pragma unroll
        for (int c = 0; c < 4; c++) acc[i][c] = 0.f;

    float as4[4], ad4[4];
#pragma unroll
    for (int c = 0; c < 4; c++) {
        as4[c] = att_src[cx * 4 + c];
        ad4[c] = att_dst[cx * 4 + c];
    }

    for (int kc = 0; kc < INF; kc += 32) {
#pragma unroll
        for (int idx = tid; idx < 128 * 32; idx += 256) {
            int r = idx >> 5, k = idx & 31;
            int gr = rowBase + r;
            xs[k][r] = (gr < N) ? x[(size_t)gr * INF + kc + k] : 0.f;
        }
#pragma unroll
        for (int idx = tid; idx < 32 * 64; idx += 256) {
            int k = idx >> 6, j = idx & 63;
            ws[k][j] = W[(size_t)(kc + k) * HID + j];
        }
        __syncthreads();

#pragma unroll
        for (int k = 0; k < 32; k++) {
            float4 wv = *(const float4*)&ws[k][cx * 4];
#pragma unroll
            for (int i = 0; i < 8; i++) {
                float xv = xs[k][ry + 16 * i];
                acc[i][0] += xv * wv.x;
                acc[i][1] += xv * wv.y;
                acc[i][2] += xv * wv.z;
                acc[i][3] += xv * wv.w;
            }
        }
        __syncthreads();
    }

#pragma unroll
    for (int i = 0; i < 8; i++) {
        int r = rowBase + ry + 16 * i;
        if (r < N) {
            float4 v = make_float4(acc[i][0], acc[i][1], acc[i][2], acc[i][3]);
            *(float4*)&g_h[(size_t)r * HID + cx * 4] = v;

            float ps = acc[i][0] * as4[0] + acc[i][1] * as4[1] +
                       acc[i][2] * as4[2] + acc[i][3] * as4[3];
            float pd = acc[i][0] * ad4[0] + acc[i][1] * ad4[1] +
                       acc[i][2] * ad4[2] + acc[i][3] * ad4[3];
#pragma unroll
            for (int o = 8; o; o >>= 1) {
                ps += __shfl_xor_sync(0xFFFFFFFFu, ps, o);
                pd += __shfl_xor_sync(0xFFFFFFFFu, pd, o);
            }
            if (cx == 0) { g_asrc[r] = ps; g_adst[r] = pd; }
        }
    }
}

// ---------------- single edge pass -------------------------------------------
// 8 lanes per edge (4 edges per warp); each lane: 2 independent float4 loads of
// h[src] and 2 independent red.v4 into agg[dst].
// w = exp(leaky_relu(a_src[s]+a_dst[d])) (max-shift omitted: logits O(10),
// alpha shift-invariant, fp32-safe). denom[d] += w from sub-lane 0.
__global__ __launch_bounds__(256) void edge_kernel(
    const int* __restrict__ ei, int E, int N)
{
    const int T = E + N;
    const int lane = threadIdx.x & 31;
    const int oct  = lane >> 3;
    const int sub  = lane & 7;

    long long warpId = ((long long)blockIdx.x * blockDim.x + threadIdx.x) >> 5;
    long long e = warpId * 4 + oct;
    if (e >= T) return;

    int s, d;
    if (e < E) { s = ei[e]; d = ei[E + e]; }
    else       { s = d = (int)(e - E); }

    float l = g_asrc[s] + g_adst[d];
    l = (l > 0.f) ? l : 0.2f * l;
    float w = expf(l);

    const float4* __restrict__ h4 = (const float4*)g_h;
    float4 a0 = __ldg(&h4[(size_t)s * 16 + sub]);
    float4 a1 = __ldg(&h4[(size_t)s * 16 + sub + 8]);

    float* ap = g_agg + (size_t)d * HID;
    red_add_v4(ap + sub * 4,       w * a0.x, w * a0.y, w * a0.z, w * a0.w);
    red_add_v4(ap + (sub + 8) * 4, w * a1.x, w * a1.y, w * a1.z, w * a1.w);

    if (sub == 0) atomicAdd(&g_denom[d], w);
}

// ---------------- colsum of relu(agg/denom + bias); re-zeroes agg ------------
// float4 per thread, 16 rows in flight per block iteration.
__global__ __launch_bounds__(256) void colsum_kernel(
    const float* __restrict__ bias, int N)
{
    const int c  = threadIdx.x & 15;    // float4 column group
    const int rg = threadIdx.x >> 4;    // row sub-group 0..15

    float4 b = ((const float4*)bias)[c];
    float4 acc = make_float4(0.f, 0.f, 0.f, 0.f);
    float4* __restrict__ agg4 = (float4*)g_agg;
    const float4 zero4 = make_float4(0.f, 0.f, 0.f, 0.f);

    for (int r = blockIdx.x * 16 + rg; r < N; r += gridDim.x * 16) {
        float inv = 1.f / g_denom[r];
        size_t idx = (size_t)r * 16 + c;
        float4 v = agg4[idx];
        agg4[idx] = zero4;                    // re-zero for next replay
        acc.x += fmaxf(v.x * inv + b.x, 0.f);
        acc.y += fmaxf(v.y * inv + b.y, 0.f);
        acc.z += fmaxf(v.z * inv + b.z, 0.f);
        acc.w += fmaxf(v.w * inv + b.w, 0.f);
    }

    __shared__ float sm[16][64];
    sm[rg][c * 4 + 0] = acc.x;
    sm[rg][c * 4 + 1] = acc.y;
    sm[rg][c * 4 + 2] = acc.z;
    sm[rg][c * 4 + 3] = acc.w;
    __syncthreads();
    if (threadIdx.x < 64) {
        float s = 0.f;
#pragma unroll
        for (int g = 0; g < 16; g++) s += sm[g][threadIdx.x];
        atomicAdd(&g_colsum[threadIdx.x], s);
    }
}

// ---------------- denom re-zero (tiny) ---------------------------------------
__global__ void denom_zero_kernel(int N) {
    int i = blockIdx.x * blockDim.x + threadIdx.x;
    if (i < N) g_denom[i] = 0.f;
}

// ---------------- final: out = (colsum/N) @ W_lin + b_lin; reset colsum ------
__global__ void final_kernel(const float* __restrict__ W_lin,
                             const float* __restrict__ b_lin,
                             float* __restrict__ out, float invN)
{
    int j = threadIdx.x;   // 64 threads
    float acc = b_lin[j];
#pragma unroll
    for (int k = 0; k < 64; k++)
        acc += (g_colsum[k] * invN) * W_lin[k * 64 + j];
    out[j] = acc;
    __syncthreads();
    g_colsum[j] = 0.f;     // reset for next replay
}

// ---------------- launch -----------------------------------------------------
extern "C" void kernel_launch(void* const* d_in, const int* in_sizes, int n_in,
                              void* d_out, int out_size)
{
    const float* x       = (const float*)d_in[0];
    const int*   ei      = (const int*)d_in[1];
    const float* W       = (const float*)d_in[2];
    const float* att_src = (const float*)d_in[3];
    const float* att_dst = (const float*)d_in[4];
    const float* bias    = (const float*)d_in[5];
    const float* W_lin   = (const float*)d_in[6];
    const float* b_lin   = (const float*)d_in[7];
    float*       out     = (float*)d_out;

    const int N = in_sizes[0] / INF;       // 100000
    const int E = in_sizes[1] / 2;         // 1600000
    const int T = E + N;

    gemm_kernel<<<(N + 127) / 128, 256>>>(x, W, att_src, att_dst, N);

    long long warps = ((long long)T + 3) / 4;          // 4 edges per warp
    long long threads = warps * 32;
    int blocks = (int)((threads + 255) / 256);
    edge_kernel<<<blocks, 256>>>(ei, E, N);

    colsum_kernel<<<1024, 256>>>(bias, N);

    denom_zero_kernel<<<(N + 255) / 256, 256>>>(N);

    final_kernel<<<1, 64>>>(W_lin, b_lin, out, 1.0f / (float)N);
}